// round 13
// baseline (speedup 1.0000x reference)
#include <cuda_runtime.h>
#include <cstdint>

#define N_ 128
#define C_ 128
#define H_ 56
#define W_ 56
#define O_ 32

#define THREADS 256           // 8 warps: r2 = wid>>2 (2 h rows), q = wid&3 (14-px window)
#define ROWS2 2
#define C_CH 16
#define NCH 8
#define M_ 96                 // 3 taps * 32 o

#define WS 132                // A smem row stride (words): 128 k + 4 pad; 16B aligned, 4-bank row spacing
#define SA_FLOATS (M_ * WS)                   // 12672
#define SX_STRIDE 72
#define SX_BUF (ROWS2 * C_CH * SX_STRIDE)     // 2304 floats per buffer
#define SMEM_BYTES ((SA_FLOATS + 2 * SX_BUF) * 4)   // 69120 B -> 2 blocks/SM

__device__ __align__(16) float g_packW[M_ * C_];     // [m][c], m = tap*32+o, tf32-rounded

extern __shared__ float smf[];

__device__ __forceinline__ void cp16(float* dst, const float* src) {
    unsigned int d = (unsigned int)__cvta_generic_to_shared(dst);
    asm volatile("cp.async.ca.shared.global [%0], [%1], 16;" :: "r"(d), "l"(src));
}
__device__ __forceinline__ uint32_t f2tf32(float v) {
    uint32_t b;
    asm("cvt.rna.tf32.f32 %0, %1;" : "=r"(b) : "f"(v));
    return b;
}
__device__ __forceinline__ void mma8(float* d, uint32_t a0, uint32_t a1, uint32_t a2,
                                     uint32_t a3, uint32_t b0, uint32_t b1) {
    asm volatile(
        "mma.sync.aligned.m16n8k8.row.col.f32.tf32.tf32.f32 "
        "{%0,%1,%2,%3}, {%4,%5,%6,%7}, {%8,%9}, {%0,%1,%2,%3};"
        : "+f"(d[0]), "+f"(d[1]), "+f"(d[2]), "+f"(d[3])
        : "r"(a0), "r"(a1), "r"(a2), "r"(a3), "r"(b0), "r"(b1));
}
__device__ __forceinline__ void ldsm4(uint32_t& a0, uint32_t& a1, uint32_t& a2,
                                      uint32_t& a3, uint32_t addr) {
    asm volatile("ldmatrix.sync.aligned.m8n8.x4.shared.b16 {%0,%1,%2,%3}, [%4];"
                 : "=r"(a0), "=r"(a1), "=r"(a2), "=r"(a3) : "r"(addr));
}

__global__ void prep_kernel(const float* __restrict__ wgt) {
    int idx = blockIdx.x * blockDim.x + threadIdx.x;
    if (idx < M_ * C_) {
        int m = idx >> 7, c = idx & 127;
        int tap = m >> 5, o = m & 31;
        g_packW[m * C_ + c] = __uint_as_float(f2tf32(wgt[(o * C_ + c) * 3 + tap]));
    }
}

__global__ void __launch_bounds__(THREADS, 2)
conv_mma_kernel(const float* __restrict__ x, float* __restrict__ out) {
    float* swA = smf;                    // A: [m][WS], k-contiguous
    float* sX0 = smf + SA_FLOATS;        // [r2][c][SX_STRIDE]; value w at idx w+4
    float* sX1 = sX0 + SX_BUF;

    const int n   = blockIdx.x;
    const int bh  = blockIdx.y;
    const int tid = threadIdx.x;
    const int wid  = tid >> 5;
    const int lane = tid & 31;
    const int r2   = wid >> 2;           // 0..1 h-row
    const int q    = wid & 3;            // 14-px window: w = 14q .. 14q+13
    const int g    = lane >> 2;          // 0..7
    const int t    = lane & 3;           // 0..3

    // per-lane ldmatrix row/col offset within an A tile
    const int a_lane = ((lane & 7) + ((lane >> 3) & 1) * 8) * WS + (lane >> 4) * 4;
    const uint32_t swA_u32 = (uint32_t)__cvta_generic_to_shared(swA);

    // ---- stage A (prepacked, L2-hot): 3072 x 16B ----
    for (int p = tid; p < (M_ * C_) / 4; p += THREADS)
        cp16(swA + (p >> 5) * WS + (p & 31) * 4, g_packW + p * 4);
    asm volatile("cp.async.commit_group;");

    // ---- zero pads: idx 3 (w=-1) and idx 60..71 ----
    for (int i = tid; i < 2 * ROWS2 * C_CH; i += THREADS) {
        float* row = sX0 + i * SX_STRIDE;           // sX0/sX1 contiguous
        row[3] = 0.0f;
#pragma unroll
        for (int z = 60; z < 72; ++z) row[z] = 0.0f;
    }

    auto stage = [&](float* buf, int ch) {
        for (int p = tid; p < ROWS2 * C_CH * 14; p += THREADS) {
            int j  = p % 14;
            int cl = (p / 14) & (C_CH - 1);
            int rr = p / (14 * C_CH);
            int hs = bh * ROWS2 + rr - 1; if (hs < 0) hs += H_;
            const float* src = x + (((size_t)n * C_ + (ch * C_CH + cl)) * H_ + hs) * W_ + j * 4;
            cp16(buf + (rr * C_CH + cl) * SX_STRIDE + 4 + j * 4, src);
        }
    };

    stage(sX0, 0);
    asm volatile("cp.async.commit_group;");

    float acc[6][2][4];
#pragma unroll
    for (int mt = 0; mt < 6; ++mt)
#pragma unroll
        for (int ni = 0; ni < 2; ++ni)
#pragma unroll
            for (int e = 0; e < 4; ++e) acc[mt][ni][e] = 0.0f;

    const int PB = 14 * q + 3 + g;       // B column base for this lane

    for (int ch = 0; ch < NCH; ++ch) {
        __syncthreads();
        if (ch + 1 < NCH) stage((ch & 1) ? sX0 : sX1, ch + 1);
        asm volatile("cp.async.commit_group;");
        if (ch < NCH - 1) asm volatile("cp.async.wait_group 1;");
        else              asm volatile("cp.async.wait_group 0;");
        __syncthreads();

        const float* buf = (ch & 1) ? sX1 : sX0;
        const float* sx  = buf + r2 * (C_CH * SX_STRIDE);

#pragma unroll
        for (int ks = 0; ks < 2; ++ks) {
            // B fragments: (k = ks*8 + t (+4), n = g + 8ni)
            const float* brow = sx + (ks * 8 + t) * SX_STRIDE + PB;
            uint32_t b0n0 = __float_as_uint(brow[0]);
            uint32_t b0n1 = __float_as_uint(brow[8]);
            uint32_t b1n0 = __float_as_uint(brow[4 * SX_STRIDE]);
            uint32_t b1n1 = __float_as_uint(brow[4 * SX_STRIDE + 8]);

            const uint32_t abase = swA_u32 +
                4u * (uint32_t)(a_lane + ch * C_CH + ks * 8);
#pragma unroll
            for (int mt = 0; mt < 6; ++mt) {
                uint32_t a0, a1, a2, a3;
                ldsm4(a0, a1, a2, a3, abase + 4u * (uint32_t)(16 * mt * WS));
                mma8(acc[mt][0], a0, a1, a2, a3, b0n0, b1n0);
                mma8(acc[mt][1], a0, a1, a2, a3, b0n1, b1n1);
            }
        }
    }

    // ---- epilogue: dump D to smem (reuse A region), shift-add taps, store ----
    __syncthreads();                      // all warps done reading swA
    {
        float* Ew = smf + wid * (M_ * 16);    // [m][16] per warp
#pragma unroll
        for (int mt = 0; mt < 6; ++mt)
#pragma unroll
            for (int ni = 0; ni < 2; ++ni) {
                int base = (16 * mt + g) * 16 + 8 * ni + 2 * t;
                *reinterpret_cast<float2*>(Ew + base) =
                    make_float2(acc[mt][ni][0], acc[mt][ni][1]);
                *reinterpret_cast<float2*>(Ew + base + 128) =            // row g+8
                    make_float2(acc[mt][ni][2], acc[mt][ni][3]);
            }
    }
    __syncthreads();

    for (int idx = tid; idx < ROWS2 * O_ * W_; idx += THREADS) {
        int w  = idx % W_;
        int o  = (idx / W_) % O_;
        int rr = idx / (W_ * O_);
        int qq = w / 14, ii = w % 14;
        const float* E = smf + (rr * 4 + qq) * (M_ * 16);
        float y = E[o * 16 + ii]
                + E[(32 + o) * 16 + ii + 1]
                + E[(64 + o) * 16 + ii + 2];
        int h = bh * ROWS2 + rr;
        out[(((size_t)n * O_ + o) * H_ + h) * W_ + w] = y;
    }
}

extern "C" void kernel_launch(void* const* d_in, const int* in_sizes, int n_in,
                              void* d_out, int out_size) {
    const float* x = (const float*)d_in[0];
    const float* w = (const float*)d_in[1];
    if (n_in >= 2 && in_sizes[0] == O_ * C_ * 3) {
        const float* tmp = x; x = w; w = tmp;
    }
    float* out = (float*)d_out;

    prep_kernel<<<(M_ * C_ + 255) / 256, 256>>>(w);

    cudaFuncSetAttribute(conv_mma_kernel,
                         cudaFuncAttributeMaxDynamicSharedMemorySize, SMEM_BYTES);
    dim3 grid(N_, H_ / ROWS2);   // 128 x 28
    conv_mma_kernel<<<grid, THREADS, SMEM_BYTES>>>(x, out);
}

// round 15
// speedup vs baseline: 1.5597x; 1.5597x over previous
#include <cuda_runtime.h>
#include <cstdint>

#define N_ 128
#define C_ 128
#define H_ 56
#define W_ 56
#define O_ 32
#define KTOT 384              // k = tap*128 + c

#define THREADS 256           // 8 warps: r = wid>>1 (4 h rows), s = wid&1
#define ROWS4 4
#define C_CH 16
#define NCH 8

#define SA_STRIDE 388         // words per m-row: 384 k + 4 pad (m*4 %32 distinct bank-groups)
#define SA_FLOATS (O_ * SA_STRIDE)             // 12416
#define SX_STRIDE 72          // (8t+g) bank pattern, conflict-free
#define SX_ROW   (C_CH * SX_STRIDE)            // 1152
#define SX_BUF   (ROWS4 * SX_ROW)              // 4608 floats per buffer
#define SMEM_BYTES ((SA_FLOATS + 2 * SX_BUF) * 4)   // 86528 B -> 2 blocks/SM

__device__ __align__(16) float g_packW[O_ * KTOT];   // [o][k], tf32-rounded

extern __shared__ float smf[];

__device__ __forceinline__ void cp16(float* dst, const float* src) {
    unsigned int d = (unsigned int)__cvta_generic_to_shared(dst);
    asm volatile("cp.async.ca.shared.global [%0], [%1], 16;" :: "r"(d), "l"(src));
}
__device__ __forceinline__ uint32_t f2tf32(float v) {
    uint32_t b;
    asm("cvt.rna.tf32.f32 %0, %1;" : "=r"(b) : "f"(v));
    return b;
}
__device__ __forceinline__ void mma8(float* d, uint32_t a0, uint32_t a1, uint32_t a2,
                                     uint32_t a3, uint32_t b0, uint32_t b1) {
    asm volatile(
        "mma.sync.aligned.m16n8k8.row.col.f32.tf32.tf32.f32 "
        "{%0,%1,%2,%3}, {%4,%5,%6,%7}, {%8,%9}, {%0,%1,%2,%3};"
        : "+f"(d[0]), "+f"(d[1]), "+f"(d[2]), "+f"(d[3])
        : "r"(a0), "r"(a1), "r"(a2), "r"(a3), "r"(b0), "r"(b1));
}
__device__ __forceinline__ void ldsm4(uint32_t& a0, uint32_t& a1, uint32_t& a2,
                                      uint32_t& a3, uint32_t addr) {
    asm volatile("ldmatrix.sync.aligned.m8n8.x4.shared.b16 {%0,%1,%2,%3}, [%4];"
                 : "=r"(a0), "=r"(a1), "=r"(a2), "=r"(a3) : "r"(addr));
}

__global__ void prep_kernel(const float* __restrict__ wgt) {
    int idx = blockIdx.x * blockDim.x + threadIdx.x;
    if (idx < O_ * KTOT) {
        int o = idx / KTOT, k = idx % KTOT;
        int tap = k >> 7, c = k & 127;
        g_packW[o * KTOT + k] = __uint_as_float(f2tf32(wgt[(o * C_ + c) * 3 + tap]));
    }
}

__global__ void __launch_bounds__(THREADS, 2)
conv_mma_kernel(const float* __restrict__ x, float* __restrict__ out) {
    float* sA  = smf;                    // [o][SA_STRIDE], k contiguous
    float* sX0 = smf + SA_FLOATS;        // [r][c_loc][SX_STRIDE]; value w at idx w+4
    float* sX1 = sX0 + SX_BUF;

    const int n   = blockIdx.x;
    const int bh  = blockIdx.y;
    const int tid = threadIdx.x;
    const int wid  = tid >> 5;
    const int lane = tid & 31;
    const int r    = wid >> 1;           // 0..3 h-row
    const int s    = wid & 1;            // 0 -> px 0..31 (4 tiles), 1 -> px 32..55 (3 tiles)
    const int g    = lane >> 2;          // 0..7
    const int t    = lane & 3;           // 0..3
    const int h    = bh * ROWS4 + r;
    const int NI   = 4 - s;

    // ldmatrix.x4 per-lane row address (R13-validated mapping), within a 16-row mi tile:
    // lane l -> row (l&7) + 8*((l>>3)&1), k word offset 4*(l>>4)
    const int a_lane = ((lane & 7) + ((lane >> 3) & 1) * 8) * SA_STRIDE + (lane >> 4) * 4;
    const uint32_t sA_u32 = (uint32_t)__cvta_generic_to_shared(sA);

    // ---- stage A (L2-hot prepacked): 3072 x 16B ----
    for (int p = tid; p < (O_ * KTOT) / 4; p += THREADS) {
        int o = p / (KTOT / 4), seg = p % (KTOT / 4);
        cp16(sA + o * SA_STRIDE + seg * 4, g_packW + p * 4);
    }
    asm volatile("cp.async.commit_group;");

    // ---- zero pads: idx 3 (w=-1) and idx 60..71 ----
    for (int i = tid; i < 2 * ROWS4 * C_CH; i += THREADS) {
        float* row = sX0 + i * SX_STRIDE;          // sX0/sX1 contiguous
        row[3] = 0.0f;
#pragma unroll
        for (int z = 60; z < 72; ++z) row[z] = 0.0f;
    }

    auto stage = [&](float* buf, int ch) {
        for (int q = tid; q < ROWS4 * C_CH * 14; q += THREADS) {
            int j  = q % 14;
            int cl = (q / 14) & (C_CH - 1);
            int r2 = q / (14 * C_CH);
            int hs = bh * ROWS4 + r2 - 1; if (hs < 0) hs += H_;
            const float* src = x + (((size_t)n * C_ + (ch * C_CH + cl)) * H_ + hs) * W_ + j * 4;
            cp16(buf + (r2 * C_CH + cl) * SX_STRIDE + 4 + j * 4, src);
        }
    };

    stage(sX0, 0);
    asm volatile("cp.async.commit_group;");

    float acc[2][4][4];
#pragma unroll
    for (int mi = 0; mi < 2; ++mi)
#pragma unroll
        for (int ni = 0; ni < 4; ++ni)
#pragma unroll
            for (int e = 0; e < 4; ++e) acc[mi][ni][e] = 0.0f;

    const int baseB = 32 * s + g + 3;

    for (int ch = 0; ch < NCH; ++ch) {
        __syncthreads();
        if (ch + 1 < NCH) stage((ch & 1) ? sX0 : sX1, ch + 1);
        asm volatile("cp.async.commit_group;");
        if (ch < NCH - 1) asm volatile("cp.async.wait_group 1;");
        else              asm volatile("cp.async.wait_group 0;");
        __syncthreads();

        const float* buf = (ch & 1) ? sX1 : sX0;
        const float* sx  = buf + r * SX_ROW;

#pragma unroll
        for (int tap = 0; tap < 3; ++tap) {
#pragma unroll
            for (int ks = 0; ks < 2; ++ks) {
                const int kg = tap * 128 + ch * C_CH + ks * 8;
                uint32_t A0[4], A1[4];
                ldsm4(A0[0], A0[1], A0[2], A0[3], sA_u32 + 4u * (uint32_t)(a_lane + kg));
                ldsm4(A1[0], A1[1], A1[2], A1[3],
                      sA_u32 + 4u * (uint32_t)(a_lane + kg + 16 * SA_STRIDE));

                const int br = (ks * 8 + t) * SX_STRIDE + baseB + tap;
                uint32_t b0[4], b1[4];
#pragma unroll
                for (int ni = 0; ni < 4; ++ni)
                    if (ni < NI) {
                        b0[ni] = __float_as_uint(sx[br + 8 * ni]);
                        b1[ni] = __float_as_uint(sx[br + 8 * ni + 4 * SX_STRIDE]);
                    }
#pragma unroll
                for (int ni = 0; ni < 4; ++ni)
                    if (ni < NI) {
                        mma8(acc[0][ni], A0[0], A0[1], A0[2], A0[3], b0[ni], b1[ni]);
                        mma8(acc[1][ni], A1[0], A1[1], A1[2], A1[3], b0[ni], b1[ni]);
                    }
            }
        }
    }

    // ---- store: lane (g,t) row o = 16mi+g (+8), px = 32s + 8ni + 2t ----
#pragma unroll
    for (int mi = 0; mi < 2; ++mi)
#pragma unroll
        for (int ni = 0; ni < 4; ++ni) {
            if (ni >= NI) continue;
            int o  = 16 * mi + g;
            int px = 32 * s + 8 * ni + 2 * t;
            float* dst = out + (((size_t)n * O_ + o) * H_ + h) * W_ + px;
            *reinterpret_cast<float2*>(dst) =
                make_float2(acc[mi][ni][0], acc[mi][ni][1]);
            *reinterpret_cast<float2*>(dst + 8 * H_ * W_) =
                make_float2(acc[mi][ni][2], acc[mi][ni][3]);   // o+8
        }
}

extern "C" void kernel_launch(void* const* d_in, const int* in_sizes, int n_in,
                              void* d_out, int out_size) {
    const float* x = (const float*)d_in[0];
    const float* w = (const float*)d_in[1];
    if (n_in >= 2 && in_sizes[0] == O_ * C_ * 3) {
        const float* tmp = x; x = w; w = tmp;
    }
    float* out = (float*)d_out;

    prep_kernel<<<(O_ * KTOT + 255) / 256, 256>>>(w);

    cudaFuncSetAttribute(conv_mma_kernel,
                         cudaFuncAttributeMaxDynamicSharedMemorySize, SMEM_BYTES);
    dim3 grid(N_, H_ / ROWS4);   // 128 x 14
    conv_mma_kernel<<<grid, THREADS, SMEM_BYTES>>>(x, out);
}